// round 1
// baseline (speedup 1.0000x reference)
#include <cuda_runtime.h>
#include <math.h>

// ---------------- problem constants ----------------
#define LSEQ 2048
#define DMODEL 768
#define NHEAD 12
#define DHEAD 64
#define NCHUNK 16
#define CSIZE 128          // chunk size (NCHUNK*CSIZE == LSEQ)
#define LN_EPS 1e-5f
#define DEN_EPS 1e-6f

// ---------------- scratch (device globals; no allocation allowed) ----------------
__device__ float g_xnorm[LSEQ * DMODEL];
__device__ float g_qkv  [LSEQ * 3 * DMODEL];
__device__ float g_sem  [LSEQ * 2 * DMODEL];
__device__ float g_ctx  [LSEQ * 2 * DMODEL];
__device__ float g_qf   [NHEAD * LSEQ * DHEAD];
__device__ float g_kf   [NHEAD * LSEQ * DHEAD];
__device__ float g_vv   [NHEAD * LSEQ * DHEAD];
__device__ float g_S    [NHEAD * NCHUNK * DHEAD * DHEAD];
__device__ float g_Z    [NHEAD * NCHUNK * DHEAD];
__device__ float g_attn [LSEQ * DMODEL];

// ---------------- LayerNorm ----------------
__global__ void ln_kernel(const float* __restrict__ x,
                          const float* __restrict__ gamma,
                          const float* __restrict__ beta) {
    int row = blockIdx.x;
    const float* xr = x + row * DMODEL;
    int tid = threadIdx.x;
    __shared__ float red[8];

    float s = 0.f;
    for (int i = tid; i < DMODEL; i += 256) s += xr[i];
    #pragma unroll
    for (int o = 16; o > 0; o >>= 1) s += __shfl_down_sync(0xffffffffu, s, o);
    if ((tid & 31) == 0) red[tid >> 5] = s;
    __syncthreads();
    if (tid < 8) {
        s = red[tid];
        #pragma unroll
        for (int o = 4; o > 0; o >>= 1) s += __shfl_down_sync(0xffu, s, o);
        if (tid == 0) red[0] = s;
    }
    __syncthreads();
    float mu = red[0] * (1.f / DMODEL);
    __syncthreads();

    float v = 0.f;
    for (int i = tid; i < DMODEL; i += 256) { float d = xr[i] - mu; v += d * d; }
    #pragma unroll
    for (int o = 16; o > 0; o >>= 1) v += __shfl_down_sync(0xffffffffu, v, o);
    if ((tid & 31) == 0) red[tid >> 5] = v;
    __syncthreads();
    if (tid < 8) {
        v = red[tid];
        #pragma unroll
        for (int o = 4; o > 0; o >>= 1) v += __shfl_down_sync(0xffu, v, o);
        if (tid == 0) red[0] = v;
    }
    __syncthreads();
    float inv = rsqrtf(red[0] * (1.f / DMODEL) + LN_EPS);

    float* yr = g_xnorm + row * DMODEL;
    for (int i = tid; i < DMODEL; i += 256)
        yr[i] = (xr[i] - mu) * inv * gamma[i] + beta[i];
}

// ---------------- SGEMM: C[M,N] = A[M,K] @ B[K,N] + bias[N] ----------------
// BM=BN=128, BK=8, TM=TN=8, 256 threads, register-prefetch double buffer.
__global__ __launch_bounds__(256)
void sgemm_bias(const float* __restrict__ A, const float* __restrict__ B,
                const float* __restrict__ bias, float* __restrict__ C,
                int M, int N, int K) {
    const int BM = 128, BN = 128, BK = 8, TM = 8, TN = 8;
    __shared__ float As[BK][BM];
    __shared__ float Bs[BK][BN];

    int tid = threadIdx.x;
    int bx = blockIdx.x;   // along N
    int by = blockIdx.y;   // along M
    int tx = tid % (BN / TN);   // 0..15
    int ty = tid / (BN / TN);   // 0..15

    int aRow = tid >> 1;            // 0..127
    int aCol = (tid & 1) * 4;       // 0 or 4
    int bRow = tid >> 5;            // 0..7
    int bCol = (tid & 31) * 4;      // 0..124

    const float* Ab = A + (size_t)(by * BM) * K;
    const float* Bb = B + bx * BN;

    float acc[TM][TN];
    #pragma unroll
    for (int i = 0; i < TM; i++)
        #pragma unroll
        for (int j = 0; j < TN; j++) acc[i][j] = 0.f;

    // preload first tile into regs
    float4 a_nxt = *(const float4*)(Ab + (size_t)aRow * K + aCol);
    float4 b_nxt = *(const float4*)(Bb + (size_t)bRow * N + bCol);

    for (int k0 = 0; k0 < K; k0 += BK) {
        // stage to shared
        As[aCol + 0][aRow] = a_nxt.x;
        As[aCol + 1][aRow] = a_nxt.y;
        As[aCol + 2][aRow] = a_nxt.z;
        As[aCol + 3][aRow] = a_nxt.w;
        *(float4*)&Bs[bRow][bCol] = b_nxt;
        __syncthreads();

        if (k0 + BK < K) {
            a_nxt = *(const float4*)(Ab + (size_t)aRow * K + (k0 + BK) + aCol);
            b_nxt = *(const float4*)(Bb + (size_t)(k0 + BK + bRow) * N + bCol);
        }

        #pragma unroll
        for (int k = 0; k < BK; k++) {
            float ra[TM], rb[TN];
            #pragma unroll
            for (int i = 0; i < TM; i += 4) *(float4*)&ra[i] = *(const float4*)&As[k][ty * TM + i];
            #pragma unroll
            for (int j = 0; j < TN; j += 4) *(float4*)&rb[j] = *(const float4*)&Bs[k][tx * TN + j];
            #pragma unroll
            for (int i = 0; i < TM; i++)
                #pragma unroll
                for (int j = 0; j < TN; j++)
                    acc[i][j] = fmaf(ra[i], rb[j], acc[i][j]);
        }
        __syncthreads();
    }

    int crow = by * BM + ty * TM;
    int ccol = bx * BN + tx * TN;
    #pragma unroll
    for (int i = 0; i < TM; i++) {
        #pragma unroll
        for (int j = 0; j < TN; j += 4) {
            float4 o;
            o.x = acc[i][j + 0] + bias[ccol + j + 0];
            o.y = acc[i][j + 1] + bias[ccol + j + 1];
            o.z = acc[i][j + 2] + bias[ccol + j + 2];
            o.w = acc[i][j + 3] + bias[ccol + j + 3];
            *(float4*)&C[(size_t)(crow + i) * N + ccol + j] = o;
        }
    }
}

// ---------------- gate + feature map + head-major relayout ----------------
__device__ __forceinline__ float softplus_f(float x) {
    return (x > 0.f) ? x + log1pf(expf(-x)) : log1pf(expf(x));
}

__global__ void features_kernel() {
    int idx = blockIdx.x * blockDim.x + threadIdx.x;
    if (idx >= LSEQ * DMODEL) return;
    int l = idx / DMODEL;
    int d = idx - l * DMODEL;

    float sa = softplus_f(g_sem[(size_t)l * 2 * DMODEL + d]);
    float sp = g_sem[(size_t)l * 2 * DMODEL + DMODEL + d];
    float ca = softplus_f(g_ctx[(size_t)l * 2 * DMODEL + d]);
    float cp = g_ctx[(size_t)l * 2 * DMODEL + DMODEL + d];
    float z  = sa * ca * cosf(sp - cp);
    float gate = 1.f / (1.f + expf(-z));

    float q = g_qkv[(size_t)l * 3 * DMODEL + d];
    float k = g_qkv[(size_t)l * 3 * DMODEL + DMODEL + d] * gate;
    float v = g_qkv[(size_t)l * 3 * DMODEL + 2 * DMODEL + d];

    int h  = d >> 6;
    int dh = d & 63;
    size_t o = (size_t)h * LSEQ * DHEAD + (size_t)l * DHEAD + dh;
    g_qf[o] = (q > 0.f) ? q + 1.f : expf(q);   // elu(q)+1
    g_kf[o] = (k > 0.f) ? k + 1.f : expf(k);   // elu(k)+1
    g_vv[o] = v;
}

// ---------------- phase A: per-chunk state sums ----------------
__global__ __launch_bounds__(256)
void chunk_sums_kernel() {
    int h = blockIdx.x / NCHUNK;
    int c = blockIdx.x % NCHUNK;
    const float* Kb = g_kf + (size_t)h * LSEQ * DHEAD + (size_t)c * CSIZE * DHEAD;
    const float* Vb = g_vv + (size_t)h * LSEQ * DHEAD + (size_t)c * CSIZE * DHEAD;

    __shared__ float ks[16][64];
    __shared__ float vs[16][64];
    int tid = threadIdx.x;
    int te = tid & 15;     // e tile
    int td = tid >> 4;     // d tile

    float acc[4][4];
    #pragma unroll
    for (int i = 0; i < 4; i++)
        #pragma unroll
        for (int j = 0; j < 4; j++) acc[i][j] = 0.f;
    float zacc[4] = {0.f, 0.f, 0.f, 0.f};

    int lr = tid >> 4;         // 0..15 load row
    int lc = (tid & 15) * 4;   // load col

    for (int p0 = 0; p0 < CSIZE; p0 += 16) {
        *(float4*)&ks[lr][lc] = *(const float4*)&Kb[(size_t)(p0 + lr) * DHEAD + lc];
        *(float4*)&vs[lr][lc] = *(const float4*)&Vb[(size_t)(p0 + lr) * DHEAD + lc];
        __syncthreads();
        #pragma unroll
        for (int p = 0; p < 16; p++) {
            float kk[4], vvv[4];
            #pragma unroll
            for (int i = 0; i < 4; i++) kk[i] = ks[p][td * 4 + i];
            #pragma unroll
            for (int j = 0; j < 4; j++) vvv[j] = vs[p][te * 4 + j];
            #pragma unroll
            for (int i = 0; i < 4; i++)
                #pragma unroll
                for (int j = 0; j < 4; j++)
                    acc[i][j] = fmaf(kk[i], vvv[j], acc[i][j]);
            if (te == 0) {
                #pragma unroll
                for (int i = 0; i < 4; i++) zacc[i] += kk[i];
            }
        }
        __syncthreads();
    }

    float* Sb = g_S + (size_t)(h * NCHUNK + c) * DHEAD * DHEAD;
    #pragma unroll
    for (int i = 0; i < 4; i++)
        #pragma unroll
        for (int j = 0; j < 4; j++)
            Sb[(size_t)(td * 4 + i) * DHEAD + te * 4 + j] = acc[i][j];
    if (te == 0) {
        float* Zb = g_Z + (size_t)(h * NCHUNK + c) * DHEAD;
        #pragma unroll
        for (int i = 0; i < 4; i++) Zb[td * 4 + i] = zacc[i];
    }
}

// ---------------- phase B: exclusive scan across chunks (per head) ----------------
__global__ __launch_bounds__(256)
void scan_states_kernel() {
    int h = blockIdx.x;
    int tid = threadIdx.x;
    float pref[16];
    #pragma unroll
    for (int i = 0; i < 16; i++) pref[i] = 0.f;
    float prefz = 0.f;

    for (int c = 0; c < NCHUNK; c++) {
        float* Sb = g_S + (size_t)(h * NCHUNK + c) * DHEAD * DHEAD;
        #pragma unroll
        for (int i = 0; i < 16; i++) {
            int idx = tid + i * 256;
            float cur = Sb[idx];
            Sb[idx] = pref[i];
            pref[i] += cur;
        }
        if (tid < DHEAD) {
            float* Zb = g_Z + (size_t)(h * NCHUNK + c) * DHEAD;
            float cur = Zb[tid];
            Zb[tid] = prefz;
            prefz += cur;
        }
    }
}

// ---------------- phase C: per-chunk causal output ----------------
// smem: K chunk (128x64) + V chunk (128x64) + P (64x64) + Z (64)
#define SMEM_C ((2 * CSIZE * DHEAD + DHEAD * DHEAD + DHEAD) * 4)

__global__ __launch_bounds__(128)
void chunk_attn_kernel() {
    int h = blockIdx.x / NCHUNK;
    int c = blockIdx.x % NCHUNK;
    extern __shared__ float sh[];
    float* Ks = sh;
    float* Vs = Ks + CSIZE * DHEAD;
    float* Ps = Vs + CSIZE * DHEAD;
    float* Zs = Ps + DHEAD * DHEAD;

    int tid = threadIdx.x;     // 128 threads, one per chunk row
    size_t base = (size_t)h * LSEQ * DHEAD + (size_t)c * CSIZE * DHEAD;

    // cooperative loads (float4)
    const float4* Kg = (const float4*)(g_kf + base);
    const float4* Vg = (const float4*)(g_vv + base);
    for (int j = tid; j < CSIZE * DHEAD / 4; j += 128) {
        ((float4*)Ks)[j] = Kg[j];
        ((float4*)Vs)[j] = Vg[j];
    }
    const float4* Pg = (const float4*)(g_S + (size_t)(h * NCHUNK + c) * DHEAD * DHEAD);
    for (int j = tid; j < DHEAD * DHEAD / 4; j += 128) ((float4*)Ps)[j] = Pg[j];
    const float4* Zg = (const float4*)(g_Z + (size_t)(h * NCHUNK + c) * DHEAD);
    if (tid < DHEAD / 4) ((float4*)Zs)[tid] = Zg[tid];
    __syncthreads();

    // load this row's q into regs
    float q[DHEAD];
    {
        const float4* qp = (const float4*)(g_qf + base + (size_t)tid * DHEAD);
        #pragma unroll
        for (int i = 0; i < DHEAD / 4; i++) {
            float4 t = qp[i];
            q[4 * i + 0] = t.x; q[4 * i + 1] = t.y; q[4 * i + 2] = t.z; q[4 * i + 3] = t.w;
        }
    }

    float out[DHEAD];
    // prefix part: out = q @ P, den = q . Z
    float den = 0.f;
    #pragma unroll
    for (int d = 0; d < DHEAD; d++) den = fmaf(q[d], Zs[d], den);
    #pragma unroll
    for (int e = 0; e < DHEAD; e++) out[e] = 0.f;
    #pragma unroll 8
    for (int d = 0; d < DHEAD; d++) {
        float qd = q[d];
        #pragma unroll
        for (int e = 0; e < DHEAD; e++)
            out[e] = fmaf(qd, Ps[d * DHEAD + e], out[e]);
    }

    // intra-chunk causal part (j loop value is uniform across lanes -> smem broadcast)
    for (int j = 0; j <= tid; j++) {
        float s = 0.f;
        const float4* kr = (const float4*)(Ks + j * DHEAD);
        #pragma unroll
        for (int i = 0; i < DHEAD / 4; i++) {
            float4 kv = kr[i];
            s = fmaf(q[4 * i + 0], kv.x, s);
            s = fmaf(q[4 * i + 1], kv.y, s);
            s = fmaf(q[4 * i + 2], kv.z, s);
            s = fmaf(q[4 * i + 3], kv.w, s);
        }
        den += s;
        const float4* vr = (const float4*)(Vs + j * DHEAD);
        #pragma unroll
        for (int i = 0; i < DHEAD / 4; i++) {
            float4 vv4 = vr[i];
            out[4 * i + 0] = fmaf(s, vv4.x, out[4 * i + 0]);
            out[4 * i + 1] = fmaf(s, vv4.y, out[4 * i + 1]);
            out[4 * i + 2] = fmaf(s, vv4.z, out[4 * i + 2]);
            out[4 * i + 3] = fmaf(s, vv4.w, out[4 * i + 3]);
        }
    }

    float inv = 1.f / (den + DEN_EPS);
    int l = c * CSIZE + tid;
    float* op = g_attn + (size_t)l * DMODEL + h * DHEAD;
    #pragma unroll
    for (int e = 0; e < DHEAD; e += 4) {
        float4 o;
        o.x = out[e + 0] * inv;
        o.y = out[e + 1] * inv;
        o.z = out[e + 2] * inv;
        o.w = out[e + 3] * inv;
        *(float4*)&op[e] = o;
    }
}

// ---------------- host launcher ----------------
extern "C" void kernel_launch(void* const* d_in, const int* in_sizes, int n_in,
                              void* d_out, int out_size) {
    const float* x      = (const float*)d_in[0];
    const float* W_qkv  = (const float*)d_in[1];
    const float* b_qkv  = (const float*)d_in[2];
    const float* W_sem  = (const float*)d_in[3];
    const float* b_sem  = (const float*)d_in[4];
    const float* W_ctx  = (const float*)d_in[5];
    const float* b_ctx  = (const float*)d_in[6];
    const float* W_proj = (const float*)d_in[7];
    const float* b_proj = (const float*)d_in[8];
    const float* ln_g   = (const float*)d_in[9];
    const float* ln_b   = (const float*)d_in[10];
    float* out = (float*)d_out;

    float *p_xnorm, *p_qkv, *p_sem, *p_ctx, *p_attn;
    cudaGetSymbolAddress((void**)&p_xnorm, g_xnorm);
    cudaGetSymbolAddress((void**)&p_qkv,   g_qkv);
    cudaGetSymbolAddress((void**)&p_sem,   g_sem);
    cudaGetSymbolAddress((void**)&p_ctx,   g_ctx);
    cudaGetSymbolAddress((void**)&p_attn,  g_attn);

    cudaFuncSetAttribute(chunk_attn_kernel,
                         cudaFuncAttributeMaxDynamicSharedMemorySize, SMEM_C);

    // 1. LayerNorm
    ln_kernel<<<LSEQ, 256>>>(x, ln_g, ln_b);

    // 2. big GEMMs
    sgemm_bias<<<dim3(3 * DMODEL / 128, LSEQ / 128), 256>>>(p_xnorm, W_qkv, b_qkv, p_qkv,
                                                            LSEQ, 3 * DMODEL, DMODEL);
    sgemm_bias<<<dim3(2 * DMODEL / 128, LSEQ / 128), 256>>>(x, W_sem, b_sem, p_sem,
                                                            LSEQ, 2 * DMODEL, DMODEL);
    sgemm_bias<<<dim3(2 * DMODEL / 128, LSEQ / 128), 256>>>(x, W_ctx, b_ctx, p_ctx,
                                                            LSEQ, 2 * DMODEL, DMODEL);

    // 3. gate + feature map + relayout
    features_kernel<<<(LSEQ * DMODEL + 255) / 256, 256>>>();

    // 4. chunked linear attention
    chunk_sums_kernel<<<NHEAD * NCHUNK, 256>>>();
    scan_states_kernel<<<NHEAD, 256>>>();
    chunk_attn_kernel<<<NHEAD * NCHUNK, 128, SMEM_C>>>();

    // 5. output projection
    sgemm_bias<<<dim3(DMODEL / 128, LSEQ / 128), 256>>>(p_attn, W_proj, b_proj, out,
                                                        LSEQ, DMODEL, DMODEL);
}

// round 3
// speedup vs baseline: 2.0455x; 2.0455x over previous
#include <cuda_runtime.h>
#include <cuda_bf16.h>
#include <math.h>
#include <stdint.h>

// ---------------- problem constants ----------------
#define LSEQ 2048
#define DMODEL 768
#define KDIM 768
#define NHEAD 12
#define DHEAD 64
#define NCHUNK 16
#define CSIZE 128
#define LN_EPS 1e-5f
#define DEN_EPS 1e-6f

// ---------------- scratch (device globals) ----------------
__device__ __align__(128) __nv_bfloat16 g_ahi[LSEQ * DMODEL];   // LN(x) hi
__device__ __align__(128) __nv_bfloat16 g_alo[LSEQ * DMODEL];   // LN(x) lo
__device__ __align__(128) __nv_bfloat16 g_xhi[LSEQ * DMODEL];   // x hi
__device__ __align__(128) __nv_bfloat16 g_xlo[LSEQ * DMODEL];   // x lo
__device__ __align__(128) __nv_bfloat16 g_wqkv_hi[2304 * KDIM]; // W_qkv^T
__device__ __align__(128) __nv_bfloat16 g_wqkv_lo[2304 * KDIM];
__device__ __align__(128) __nv_bfloat16 g_wsc_hi[3072 * KDIM];  // [W_sem;W_ctx]^T
__device__ __align__(128) __nv_bfloat16 g_wsc_lo[3072 * KDIM];
__device__ __align__(128) __nv_bfloat16 g_wpr_hi[768 * KDIM];   // W_proj^T
__device__ __align__(128) __nv_bfloat16 g_wpr_lo[768 * KDIM];
__device__ __align__(128) __nv_bfloat16 g_athi[LSEQ * DMODEL];  // attn out hi
__device__ __align__(128) __nv_bfloat16 g_atlo[LSEQ * DMODEL];  // attn out lo
__device__ __align__(128) float g_bsc[3072];
__device__ __align__(128) float g_qkv[LSEQ * 3 * DMODEL];
__device__ __align__(128) float g_semctx[LSEQ * 3072];
__device__ float g_qf[NHEAD * LSEQ * DHEAD];
__device__ float g_kf[NHEAD * LSEQ * DHEAD];
__device__ float g_vv[NHEAD * LSEQ * DHEAD];
__device__ float g_S [NHEAD * NCHUNK * DHEAD * DHEAD];
__device__ float g_Z [NHEAD * NCHUNK * DHEAD];

// ---------------- PTX helpers (family-portable only) ----------------
__device__ __forceinline__ uint32_t smem_u32(const void* p) {
    uint32_t a;
    asm("{ .reg .u64 t; cvta.to.shared.u64 t, %1; cvt.u32.u64 %0, t; }" : "=r"(a) : "l"(p));
    return a;
}
__device__ __forceinline__ void cp_async16(uint32_t dst, const void* src) {
    asm volatile("cp.async.cg.shared.global [%0], [%1], 16;" :: "r"(dst), "l"(src));
}
__device__ __forceinline__ void cp_commit() {
    asm volatile("cp.async.commit_group;" ::: "memory");
}
__device__ __forceinline__ void cp_wait1() {
    asm volatile("cp.async.wait_group 1;" ::: "memory");
}
#define LDSM4(r0, r1, r2, r3, a) \
    asm volatile("ldmatrix.sync.aligned.m8n8.x4.shared.b16 {%0,%1,%2,%3}, [%4];" \
                 : "=r"(r0), "=r"(r1), "=r"(r2), "=r"(r3) : "r"(a))
#define MMA16816(d, a0, a1, a2, a3, b0, b1) \
    asm volatile("mma.sync.aligned.m16n8k16.row.col.f32.bf16.bf16.f32 " \
                 "{%0,%1,%2,%3}, {%4,%5,%6,%7}, {%8,%9}, {%0,%1,%2,%3};" \
                 : "+f"((d)[0]), "+f"((d)[1]), "+f"((d)[2]), "+f"((d)[3]) \
                 : "r"(a0), "r"(a1), "r"(a2), "r"(a3), "r"(b0), "r"(b1))

// ---------------- GEMM: C[2048,Ntot] = A @ B^T + bias (bf16x3 fused) ----------------
// A(hi/lo): [2048,768] bf16 row-major. B^T(hi/lo): [Ntot,768] bf16 row-major.
// C = Ahi*Bhi + Ahi*Blo + Alo*Bhi, fp32 accum, exact to ~1e-6.
#define BK 32
#define ROWB 80                       // padded smem row stride (bytes) -> conflict-free
#define TILEB (128 * ROWB)            // 10240 B per 128x32 tile
#define STAGEB (4 * TILEB)            // Ahi, Alo, Bhi, Blo
#define NSTAGE 2
#define GEMM_SMEM (NSTAGE * STAGEB)   // 81920 B
#define NKT (KDIM / BK)               // 24

__device__ __forceinline__ void g_load_stage(
    uint32_t smem_base, int s, int tid,
    const __nv_bfloat16* a0, const __nv_bfloat16* a1,
    const __nv_bfloat16* b0, const __nv_bfloat16* b1)
{
    uint32_t stb = smem_base + (uint32_t)(s & (NSTAGE - 1)) * STAGEB;
    int kk = s * BK;
    #pragma unroll
    for (int t = 0; t < 4; t++) {
        const __nv_bfloat16* base = (t == 0) ? a0 : (t == 1) ? a1 : (t == 2) ? b0 : b1;
        #pragma unroll
        for (int i = 0; i < 2; i++) {
            int c = tid + i * 256;          // 0..511
            int r = c >> 2;
            int seg = c & 3;
            cp_async16(stb + (uint32_t)t * TILEB + (uint32_t)(r * ROWB + seg * 16),
                       base + (size_t)r * KDIM + kk + seg * 8);
        }
    }
}

__global__ __launch_bounds__(256, 2)
void gemm_mma(const __nv_bfloat16* __restrict__ Ahi, const __nv_bfloat16* __restrict__ Alo,
              const __nv_bfloat16* __restrict__ BhiT, const __nv_bfloat16* __restrict__ BloT,
              const float* __restrict__ bias, float* __restrict__ C, int Ntot)
{
    extern __shared__ __align__(128) char smem[];
    const int tid = threadIdx.x;
    const int wid = tid >> 5;
    const int lane = tid & 31;
    const int wm = wid & 1;        // M: 2 x 64
    const int wn = wid >> 1;       // N: 4 x 32
    const int bx = blockIdx.x, by = blockIdx.y;

    uint32_t smem_base = smem_u32(smem);

    const __nv_bfloat16* a0 = Ahi + (size_t)by * 128 * KDIM;
    const __nv_bfloat16* a1 = Alo + (size_t)by * 128 * KDIM;
    const __nv_bfloat16* b0 = BhiT + (size_t)bx * 128 * KDIM;
    const __nv_bfloat16* b1 = BloT + (size_t)bx * 128 * KDIM;

    float acc[4][4][4];
    #pragma unroll
    for (int i = 0; i < 4; i++)
        #pragma unroll
        for (int j = 0; j < 4; j++)
            #pragma unroll
            for (int t = 0; t < 4; t++) acc[i][j][t] = 0.f;

    // per-lane ldmatrix addressing components
    const uint32_t a_row = (uint32_t)(lane & 15);
    const uint32_t a_byt = (uint32_t)((lane >> 4) * 16);
    const uint32_t b_row = (uint32_t)((lane & 7) + ((lane >> 4) << 3));
    const uint32_t b_byt = (uint32_t)(((lane >> 3) & 1) * 16);

    // prologue
    g_load_stage(smem_base, 0, tid, a0, a1, b0, b1);
    cp_commit();

    for (int s = 0; s < NKT; s++) {
        if (s + 1 < NKT) g_load_stage(smem_base, s + 1, tid, a0, a1, b0, b1);
        cp_commit();
        cp_wait1();
        __syncthreads();

        uint32_t stb = smem_base + (uint32_t)(s & (NSTAGE - 1)) * STAGEB;
        #pragma unroll
        for (int pass = 0; pass < 3; pass++) {
            uint32_t At = stb + ((pass < 2) ? 0u : (uint32_t)TILEB);
            uint32_t Bt = stb + ((pass == 1) ? 3u * TILEB : 2u * TILEB);
            #pragma unroll
            for (int k16 = 0; k16 < 2; k16++) {
                uint32_t a[4][4];
                #pragma unroll
                for (int mt = 0; mt < 4; mt++) {
                    uint32_t addr = At + (uint32_t)(wm * 64 + mt * 16 + a_row) * ROWB
                                  + (uint32_t)(k16 * 32) + a_byt;
                    LDSM4(a[mt][0], a[mt][1], a[mt][2], a[mt][3], addr);
                }
                uint32_t b[2][4];
                #pragma unroll
                for (int nb = 0; nb < 2; nb++) {
                    uint32_t addr = Bt + (uint32_t)(wn * 32 + nb * 16 + b_row) * ROWB
                                  + (uint32_t)(k16 * 32) + b_byt;
                    LDSM4(b[nb][0], b[nb][1], b[nb][2], b[nb][3], addr);
                }
                #pragma unroll
                for (int mt = 0; mt < 4; mt++)
                    #pragma unroll
                    for (int nt = 0; nt < 4; nt++)
                        MMA16816(acc[mt][nt],
                                 a[mt][0], a[mt][1], a[mt][2], a[mt][3],
                                 b[nt >> 1][(nt & 1) * 2], b[nt >> 1][(nt & 1) * 2 + 1]);
            }
        }
        __syncthreads();
    }

    // epilogue: bias + fp32 store
    int r0 = by * 128 + wm * 64 + (lane >> 2);
    int c0 = bx * 128 + wn * 32 + (lane & 3) * 2;
    #pragma unroll
    for (int mt = 0; mt < 4; mt++) {
        #pragma unroll
        for (int nt = 0; nt < 4; nt++) {
            int r = r0 + mt * 16;
            int c = c0 + nt * 8;
            float2 v0 = { acc[mt][nt][0] + bias[c], acc[mt][nt][1] + bias[c + 1] };
            float2 v1 = { acc[mt][nt][2] + bias[c], acc[mt][nt][3] + bias[c + 1] };
            *(float2*)&C[(size_t)r * Ntot + c] = v0;
            *(float2*)&C[(size_t)(r + 8) * Ntot + c] = v1;
        }
    }
}

// ---------------- weight transpose + bf16 split ----------------
__global__ void transpose_split(const float* __restrict__ W, int N,
                                __nv_bfloat16* __restrict__ hiT,
                                __nv_bfloat16* __restrict__ loT, int rowOff)
{
    __shared__ float tile[32][33];
    int n0 = blockIdx.x * 32, k0 = blockIdx.y * 32;
    int tx = threadIdx.x, ty = threadIdx.y;   // (32, 8)
    #pragma unroll
    for (int i = 0; i < 4; i++)
        tile[ty + i * 8][tx] = W[(size_t)(k0 + ty + i * 8) * N + n0 + tx];
    __syncthreads();
    #pragma unroll
    for (int i = 0; i < 4; i++) {
        int n = ty + i * 8;
        float v = tile[tx][n];
        __nv_bfloat16 h = __float2bfloat16(v);
        __nv_bfloat16 l = __float2bfloat16(v - __bfloat162float(h));
        size_t o = (size_t)(rowOff + n0 + n) * KDIM + k0 + tx;
        hiT[o] = h;
        loT[o] = l;
    }
}

__global__ void concat_bias(const float* __restrict__ bs, const float* __restrict__ bc) {
    int i = blockIdx.x * 256 + threadIdx.x;
    if (i < 1536) g_bsc[i] = bs[i];
    else if (i < 3072) g_bsc[i] = bc[i - 1536];
}

// ---------------- LayerNorm + split (also splits raw x) ----------------
__global__ void ln_split_kernel(const float* __restrict__ x,
                                const float* __restrict__ gamma,
                                const float* __restrict__ beta) {
    int row = blockIdx.x;
    const float* xr = x + (size_t)row * DMODEL;
    int tid = threadIdx.x;
    __shared__ float red[8];

    float s = 0.f;
    for (int i = tid; i < DMODEL; i += 256) s += xr[i];
    #pragma unroll
    for (int o = 16; o > 0; o >>= 1) s += __shfl_down_sync(0xffffffffu, s, o);
    if ((tid & 31) == 0) red[tid >> 5] = s;
    __syncthreads();
    if (tid < 8) {
        s = red[tid];
        #pragma unroll
        for (int o = 4; o > 0; o >>= 1) s += __shfl_down_sync(0xffu, s, o);
        if (tid == 0) red[0] = s;
    }
    __syncthreads();
    float mu = red[0] * (1.f / DMODEL);
    __syncthreads();

    float v = 0.f;
    for (int i = tid; i < DMODEL; i += 256) { float d = xr[i] - mu; v += d * d; }
    #pragma unroll
    for (int o = 16; o > 0; o >>= 1) v += __shfl_down_sync(0xffffffffu, v, o);
    if ((tid & 31) == 0) red[tid >> 5] = v;
    __syncthreads();
    if (tid < 8) {
        v = red[tid];
        #pragma unroll
        for (int o = 4; o > 0; o >>= 1) v += __shfl_down_sync(0xffu, v, o);
        if (tid == 0) red[0] = v;
    }
    __syncthreads();
    float inv = rsqrtf(red[0] * (1.f / DMODEL) + LN_EPS);

    for (int i = tid; i < DMODEL; i += 256) {
        float xv = xr[i];
        float ln = (xv - mu) * inv * gamma[i] + beta[i];
        __nv_bfloat16 h = __float2bfloat16(ln);
        g_ahi[(size_t)row * DMODEL + i] = h;
        g_alo[(size_t)row * DMODEL + i] = __float2bfloat16(ln - __bfloat162float(h));
        __nv_bfloat16 xh = __float2bfloat16(xv);
        g_xhi[(size_t)row * DMODEL + i] = xh;
        g_xlo[(size_t)row * DMODEL + i] = __float2bfloat16(xv - __bfloat162float(xh));
    }
}

// ---------------- gate + feature map + head-major relayout ----------------
__device__ __forceinline__ float softplus_f(float x) {
    return (x > 0.f) ? x + log1pf(expf(-x)) : log1pf(expf(x));
}

__global__ void features_kernel() {
    int idx = blockIdx.x * blockDim.x + threadIdx.x;
    if (idx >= LSEQ * DMODEL) return;
    int l = idx / DMODEL;
    int d = idx - l * DMODEL;

    const float* scr = g_semctx + (size_t)l * 3072;
    float sa = softplus_f(scr[d]);
    float sp = scr[768 + d];
    float ca = softplus_f(scr[1536 + d]);
    float cp = scr[2304 + d];
    float z = sa * ca * cosf(sp - cp);
    float gate = 1.f / (1.f + expf(-z));

    float q = g_qkv[(size_t)l * 3 * DMODEL + d];
    float k = g_qkv[(size_t)l * 3 * DMODEL + DMODEL + d] * gate;
    float v = g_qkv[(size_t)l * 3 * DMODEL + 2 * DMODEL + d];

    int h = d >> 6;
    int dh = d & 63;
    size_t o = (size_t)h * LSEQ * DHEAD + (size_t)l * DHEAD + dh;
    g_qf[o] = (q > 0.f) ? q + 1.f : expf(q);
    g_kf[o] = (k > 0.f) ? k + 1.f : expf(k);
    g_vv[o] = v;
}

// ---------------- phase A: per-chunk state sums ----------------
__global__ __launch_bounds__(256)
void chunk_sums_kernel() {
    int h = blockIdx.x / NCHUNK;
    int c = blockIdx.x % NCHUNK;
    const float* Kb = g_kf + (size_t)h * LSEQ * DHEAD + (size_t)c * CSIZE * DHEAD;
    const float* Vb = g_vv + (size_t)h * LSEQ * DHEAD + (size_t)c * CSIZE * DHEAD;

    __shared__ float ks[16][64];
    __shared__ float vs[16][64];
    int tid = threadIdx.x;
    int te = tid & 15;
    int td = tid >> 4;

    float acc[4][4];
    #pragma unroll
    for (int i = 0; i < 4; i++)
        #pragma unroll
        for (int j = 0; j < 4; j++) acc[i][j] = 0.f;
    float zacc[4] = {0.f, 0.f, 0.f, 0.f};

    int lr = tid >> 4;
    int lc = (tid & 15) * 4;

    for (int p0 = 0; p0 < CSIZE; p0 += 16) {
        *(float4*)&ks[lr][lc] = *(const float4*)&Kb[(size_t)(p0 + lr) * DHEAD + lc];
        *(float4*)&vs[lr][lc] = *(const float4*)&Vb[(size_t)(p0 + lr) * DHEAD + lc];
        __syncthreads();
        #pragma unroll
        for (int p = 0; p < 16; p++) {
            float kk[4], vvv[4];
            #pragma unroll
            for (int i = 0; i < 4; i++) kk[i] = ks[p][td * 4 + i];
            #pragma unroll
            for (int j = 0; j < 4; j++) vvv[j] = vs[p][te * 4 + j];
            #pragma unroll
            for (int i = 0; i < 4; i++)
                #pragma unroll
                for (int j = 0; j < 4; j++)
                    acc[i][j] = fmaf(kk[i], vvv[j], acc[i][j]);
            if (te == 0) {
                #pragma unroll
                for (int i = 0; i < 4; i++) zacc[i] += kk[i];
            }
        }
        __syncthreads();
    }

    float* Sb = g_S + (size_t)(h * NCHUNK + c) * DHEAD * DHEAD;
    #pragma unroll
    for (int i = 0; i < 4; i++)
        #pragma unroll
        for (int j = 0; j < 4; j++)
            Sb[(size_t)(td * 4 + i) * DHEAD + te * 4 + j] = acc[i][j];
    if (te == 0) {
        float* Zb = g_Z + (size_t)(h * NCHUNK + c) * DHEAD;
        #pragma unroll
        for (int i = 0; i < 4; i++) Zb[td * 4 + i] = zacc[i];
    }
}

// ---------------- phase B: exclusive scan over chunks ----------------
__global__ __launch_bounds__(256)
void scan_states_kernel() {
    int h = blockIdx.x;
    int tid = threadIdx.x;
    float pref[16];
    #pragma unroll
    for (int i = 0; i < 16; i++) pref[i] = 0.f;
    float prefz = 0.f;

    for (int c = 0; c < NCHUNK; c++) {
        float* Sb = g_S + (size_t)(h * NCHUNK + c) * DHEAD * DHEAD;
        #pragma unroll
        for (int i = 0; i < 16; i++) {
            int idx = tid + i * 256;
            float cur = Sb[idx];
            Sb[idx] = pref[i];
            pref[i] += cur;
        }
        if (tid < DHEAD) {
            float* Zb = g_Z + (size_t)(h * NCHUNK + c) * DHEAD;
            float cur = Zb[tid];
            Zb[tid] = prefz;
            prefz += cur;
        }
    }
}

// ---------------- phase C: per-chunk causal output + bf16 split ----------------
#define SMEM_C ((2 * CSIZE * DHEAD + DHEAD * DHEAD + DHEAD) * 4)

__global__ __launch_bounds__(128)
void chunk_attn_kernel() {
    int h = blockIdx.x / NCHUNK;
    int c = blockIdx.x % NCHUNK;
    extern __shared__ float sh[];
    float* Ks = sh;
    float* Vs = Ks + CSIZE * DHEAD;
    float* Ps = Vs + CSIZE * DHEAD;
    float* Zs = Ps + DHEAD * DHEAD;

    int tid = threadIdx.x;
    size_t base = (size_t)h * LSEQ * DHEAD + (size_t)c * CSIZE * DHEAD;

    const float4* Kg = (const float4*)(g_kf + base);
    const float4* Vg = (const float4*)(g_vv + base);
    for (int j = tid; j < CSIZE * DHEAD / 4; j += 128) {
        ((float4*)Ks)[j] = Kg[j];
        ((float4*)Vs)[j] = Vg[j];
    }
    const float4* Pg = (const float4*)(g_S + (size_t)(h * NCHUNK + c) * DHEAD * DHEAD);
    for (int j = tid; j < DHEAD * DHEAD / 4; j += 128) ((float4*)Ps)[j] = Pg[j];
    const float4* Zg = (const float4*)(g_Z + (size_t)(h * NCHUNK + c) * DHEAD);
    if (tid < DHEAD / 4) ((float4*)Zs)[tid] = Zg[tid];
    __syncthreads();

    float q[DHEAD];
    {
        const float4* qp = (const float4*)(g_qf + base + (size_t)tid * DHEAD);
        #pragma unroll
        for (int i = 0; i < DHEAD / 4; i++) {
            float4 t = qp[i];
            q[4 * i + 0] = t.x; q[4 * i + 1] = t.y; q[4 * i + 2] = t.z; q[4 * i + 3] = t.w;
        }
    }

    float out[DHEAD];
    float den = 0.f;
    #pragma unroll
    for (int d = 0; d < DHEAD; d++) den = fmaf(q[d], Zs[d], den);
    #pragma unroll
    for (int e = 0; e < DHEAD; e++) out[e] = 0.f;
    #pragma unroll 8
    for (int d = 0; d < DHEAD; d++) {
        float qd = q[d];
        #pragma unroll
        for (int e = 0; e < DHEAD; e++)
            out[e] = fmaf(qd, Ps[d * DHEAD + e], out[e]);
    }

    for (int j = 0; j <= tid; j++) {
        float s = 0.f;
        const float4* kr = (const float4*)(Ks + j * DHEAD);
        #pragma unroll
        for (int i = 0; i < DHEAD / 4; i++) {
            float4 kv = kr[i];
            s = fmaf(q[4 * i + 0], kv.x, s);
            s = fmaf(q[4 * i + 1], kv.y, s);
            s = fmaf(q[4 * i + 2], kv.z, s);
            s = fmaf(q[4 * i + 3], kv.w, s);
        }
        den += s;
        const float4* vr = (const float4*)(Vs + j * DHEAD);
        #pragma unroll
        for (int i = 0; i < DHEAD / 4; i++) {
            float4 vv4 = vr[i];
            out[4 * i + 0] = fmaf(s, vv4.x, out[4 * i + 0]);
            out[4 * i + 1] = fmaf(s, vv4.y, out[4 * i + 1]);
            out[4 * i + 2] = fmaf(s, vv4.z, out[4 * i + 2]);
            out[4 * i + 3] = fmaf(s, vv4.w, out[4 * i + 3]);
        }
    }

    float inv = 1.f / (den + DEN_EPS);
    int l = c * CSIZE + tid;
    __nv_bfloat16* oh = g_athi + (size_t)l * DMODEL + h * DHEAD;
    __nv_bfloat16* ol = g_atlo + (size_t)l * DMODEL + h * DHEAD;
    #pragma unroll
    for (int e = 0; e < DHEAD; e++) {
        float v = out[e] * inv;
        __nv_bfloat16 hh = __float2bfloat16(v);
        oh[e] = hh;
        ol[e] = __float2bfloat16(v - __bfloat162float(hh));
    }
}

// ---------------- host launcher ----------------
extern "C" void kernel_launch(void* const* d_in, const int* in_sizes, int n_in,
                              void* d_out, int out_size) {
    const float* x      = (const float*)d_in[0];
    const float* W_qkv  = (const float*)d_in[1];
    const float* b_qkv  = (const float*)d_in[2];
    const float* W_sem  = (const float*)d_in[3];
    const float* b_sem  = (const float*)d_in[4];
    const float* W_ctx  = (const float*)d_in[5];
    const float* b_ctx  = (const float*)d_in[6];
    const float* W_proj = (const float*)d_in[7];
    const float* b_proj = (const float*)d_in[8];
    const float* ln_g   = (const float*)d_in[9];
    const float* ln_b   = (const float*)d_in[10];
    float* out = (float*)d_out;

    __nv_bfloat16 *p_ahi, *p_alo, *p_xhi, *p_xlo;
    __nv_bfloat16 *p_wqh, *p_wql, *p_wsh, *p_wsl, *p_wph, *p_wpl, *p_ath, *p_atl;
    float *p_bsc, *p_qkv, *p_semctx;
    cudaGetSymbolAddress((void**)&p_ahi, g_ahi);
    cudaGetSymbolAddress((void**)&p_alo, g_alo);
    cudaGetSymbolAddress((void**)&p_xhi, g_xhi);
    cudaGetSymbolAddress((void**)&p_xlo, g_xlo);
    cudaGetSymbolAddress((void**)&p_wqh, g_wqkv_hi);
    cudaGetSymbolAddress((void**)&p_wql, g_wqkv_lo);
    cudaGetSymbolAddress((void**)&p_wsh, g_wsc_hi);
    cudaGetSymbolAddress((void**)&p_wsl, g_wsc_lo);
    cudaGetSymbolAddress((void**)&p_wph, g_wpr_hi);
    cudaGetSymbolAddress((void**)&p_wpl, g_wpr_lo);
    cudaGetSymbolAddress((void**)&p_ath, g_athi);
    cudaGetSymbolAddress((void**)&p_atl, g_atlo);
    cudaGetSymbolAddress((void**)&p_bsc, g_bsc);
    cudaGetSymbolAddress((void**)&p_qkv, g_qkv);
    cudaGetSymbolAddress((void**)&p_semctx, g_semctx);

    cudaFuncSetAttribute(gemm_mma, cudaFuncAttributeMaxDynamicSharedMemorySize, GEMM_SMEM);
    cudaFuncSetAttribute(chunk_attn_kernel, cudaFuncAttributeMaxDynamicSharedMemorySize, SMEM_C);

    dim3 t32x8(32, 8);
    // weight prep
    transpose_split<<<dim3(2304 / 32, 768 / 32), t32x8>>>(W_qkv, 2304, p_wqh, p_wql, 0);
    transpose_split<<<dim3(1536 / 32, 768 / 32), t32x8>>>(W_sem, 1536, p_wsh, p_wsl, 0);
    transpose_split<<<dim3(1536 / 32, 768 / 32), t32x8>>>(W_ctx, 1536, p_wsh, p_wsl, 1536);
    transpose_split<<<dim3(768 / 32, 768 / 32), t32x8>>>(W_proj, 768, p_wph, p_wpl, 0);
    concat_bias<<<12, 256>>>(b_sem, b_ctx);

    // LN + activation splits
    ln_split_kernel<<<LSEQ, 256>>>(x, ln_g, ln_b);

    // tensor-core GEMMs (mma.sync, family-portable)
    gemm_mma<<<dim3(2304 / 128, LSEQ / 128), 256, GEMM_SMEM>>>(p_ahi, p_alo, p_wqh, p_wql,
                                                               b_qkv, p_qkv, 2304);
    gemm_mma<<<dim3(3072 / 128, LSEQ / 128), 256, GEMM_SMEM>>>(p_xhi, p_xlo, p_wsh, p_wsl,
                                                               p_bsc, p_semctx, 3072);

    // gate + feature map
    features_kernel<<<(LSEQ * DMODEL + 255) / 256, 256>>>();

    // chunked linear attention
    chunk_sums_kernel<<<NHEAD * NCHUNK, 256>>>();
    scan_states_kernel<<<NHEAD, 256>>>();
    chunk_attn_kernel<<<NHEAD * NCHUNK, 128, SMEM_C>>>();

    // output projection
    gemm_mma<<<dim3(768 / 128, LSEQ / 128), 256, GEMM_SMEM>>>(p_ath, p_atl, p_wph, p_wpl,
                                                              b_proj, out, 768);
}